// round 11
// baseline (speedup 1.0000x reference)
#include <cuda_runtime.h>
#include <cuda_fp16.h>

#define NV 4096            // nodes per graph
#define NB 32              // batch size (== warp size, load-bearing)
#define BN (NV * NB)       // 131072
#define CAP 256            // ELL row capacity (mean degree 128, +11 sigma headroom)
#define CSTRIDE 32         // counter padding: 1 counter per 128B line

// ---- scratch (device globals; counters zero at entry: BSS on first call,
//      self-zeroed by k_mu/k_dx on every call) ----
__device__ float  g_xt   [BN];           // x,  node-major [node][batch] (fp32)
__device__ float  g_fxt  [BN];           // tanh(x), node-major (fp32, epilogue)
__device__ __half g_fxt16[BN];           // tanh(x), node-major (fp16, gathers)
__device__ float  g_epst [BN];           // eps, node-major (fp32, epilogue)
__device__ __half g_epst16[BN];          // eps, node-major (fp16, gathers)
__device__ int    g_cnt_dst[NV * CSTRIDE];   // padded: index node*32
__device__ int    g_cnt_src[NV * CSTRIDE];
__device__ float2 g_ellF[NV * CAP];      // rows keyed by dst: (src*32, w)
__device__ float2 g_ellB[NV * CAP];      // rows keyed by src: (dst*32, w)

// Transpose x [B,N] -> node-major, apply tanh (fp32 + fp16 copies).
__global__ void k_prep(const float* __restrict__ x) {
    __shared__ float s[32][33];
    int tx = threadIdx.x & 31;
    int ty = threadIdx.x >> 5;
    int i0 = blockIdx.x * 32;

    s[ty][tx] = x[ty * NV + i0 + tx];          // batch-major read (coalesced)
    __syncthreads();

    float xv = s[tx][ty];
    float fx = tanhf(xv);
    int o = (i0 + ty) * NB + tx;               // node-major write (coalesced)
    g_xt[o]    = xv;
    g_fxt[o]   = fx;
    g_fxt16[o] = __float2half_rn(fx);
}

// Build both ELL structures; 4 edges/thread, padded counters (R6-proven).
__global__ void k_build(const float* __restrict__ w,
                        const int*   __restrict__ esrc,
                        const int*   __restrict__ edst, int E) {
    int t  = blockIdx.x * blockDim.x + threadIdx.x;
    int e0 = t << 2;
    if (e0 >= E) return;
    if (e0 + 4 <= E) {
        int4   s4 = *(const int4*)  (esrc + e0);
        int4   d4 = *(const int4*)  (edst + e0);
        float4 w4 = *(const float4*)(w    + e0);
        int p0 = atomicAdd(&g_cnt_dst[d4.x << 5], 1);
        int p1 = atomicAdd(&g_cnt_dst[d4.y << 5], 1);
        int p2 = atomicAdd(&g_cnt_dst[d4.z << 5], 1);
        int p3 = atomicAdd(&g_cnt_dst[d4.w << 5], 1);
        int q0 = atomicAdd(&g_cnt_src[s4.x << 5], 1);
        int q1 = atomicAdd(&g_cnt_src[s4.y << 5], 1);
        int q2 = atomicAdd(&g_cnt_src[s4.z << 5], 1);
        int q3 = atomicAdd(&g_cnt_src[s4.w << 5], 1);
        if (p0 < CAP) g_ellF[(d4.x << 8) + p0] = make_float2(__int_as_float(s4.x << 5), w4.x);
        if (p1 < CAP) g_ellF[(d4.y << 8) + p1] = make_float2(__int_as_float(s4.y << 5), w4.y);
        if (p2 < CAP) g_ellF[(d4.z << 8) + p2] = make_float2(__int_as_float(s4.z << 5), w4.z);
        if (p3 < CAP) g_ellF[(d4.w << 8) + p3] = make_float2(__int_as_float(s4.w << 5), w4.w);
        if (q0 < CAP) g_ellB[(s4.x << 8) + q0] = make_float2(__int_as_float(d4.x << 5), w4.x);
        if (q1 < CAP) g_ellB[(s4.y << 8) + q1] = make_float2(__int_as_float(d4.y << 5), w4.y);
        if (q2 < CAP) g_ellB[(s4.z << 8) + q2] = make_float2(__int_as_float(d4.z << 5), w4.z);
        if (q3 < CAP) g_ellB[(s4.w << 8) + q3] = make_float2(__int_as_float(d4.w << 5), w4.w);
    } else {
        for (int e = e0; e < E; e++) {
            int s = esrc[e], d = edst[e];
            float wt = w[e];
            int p = atomicAdd(&g_cnt_dst[d << 5], 1);
            if (p < CAP) g_ellF[(d << 8) + p] = make_float2(__int_as_float(s << 5), wt);
            int q = atomicAdd(&g_cnt_src[s << 5], 1);
            if (q < CAP) g_ellB[(s << 8) + q] = make_float2(__int_as_float(d << 5), wt);
        }
    }
}

// SpMM inner loop over smem-staged row [jb,je): LDS.64 broadcast of
// (colOff, w), fp16 1-sector-pair gathers via pre-offset lane pointer,
// unroll-8 for 8 gathers in flight. (R5-proven structure.)
__device__ __forceinline__ float spmm_smem(const float2* row,
                                           const __half* __restrict__ tabl,
                                           int jb, int je) {
    float a0 = 0.f, a1 = 0.f, a2 = 0.f, a3 = 0.f;
    int j = jb;
    for (; j + 8 <= je; j += 8) {
        float2 e0 = row[j + 0]; float2 e1 = row[j + 1];
        float2 e2 = row[j + 2]; float2 e3 = row[j + 3];
        float2 e4 = row[j + 4]; float2 e5 = row[j + 5];
        float2 e6 = row[j + 6]; float2 e7 = row[j + 7];
        float v0 = __half2float(tabl[__float_as_int(e0.x)]);
        float v1 = __half2float(tabl[__float_as_int(e1.x)]);
        float v2 = __half2float(tabl[__float_as_int(e2.x)]);
        float v3 = __half2float(tabl[__float_as_int(e3.x)]);
        float v4 = __half2float(tabl[__float_as_int(e4.x)]);
        float v5 = __half2float(tabl[__float_as_int(e5.x)]);
        float v6 = __half2float(tabl[__float_as_int(e6.x)]);
        float v7 = __half2float(tabl[__float_as_int(e7.x)]);
        a0 = fmaf(e0.y, v0, a0); a1 = fmaf(e1.y, v1, a1);
        a2 = fmaf(e2.y, v2, a2); a3 = fmaf(e3.y, v3, a3);
        a0 = fmaf(e4.y, v4, a0); a1 = fmaf(e5.y, v5, a1);
        a2 = fmaf(e6.y, v6, a2); a3 = fmaf(e7.y, v7, a3);
    }
    for (; j < je; j++) {
        float2 e0 = row[j];
        a0 = fmaf(e0.y, __half2float(tabl[__float_as_int(e0.x)]), a0);
    }
    return (a0 + a1) + (a2 + a3);
}

// Forward SpMM: mu = sum w * fx[src]; eps = x - mu (fp32 + fp16);
// mu written straight to out[0] batch-major (scattered 4B stores).
__global__ void __launch_bounds__(256, 8) k_mu(float* __restrict__ out) {
    __shared__ float2 srow[2][CAP];
    __shared__ float  part[2][4][32];
    int warp  = threadIdx.x >> 5;
    int lane  = threadIdx.x & 31;
    int local = warp >> 2;
    int q     = warp & 3;
    int node0 = blockIdx.x << 1;

    int n0 = min(g_cnt_dst[node0 << 5],       CAP);
    int n1 = min(g_cnt_dst[(node0 + 1) << 5], CAP);
    for (int i = threadIdx.x; i < n0; i += 256) srow[0][i] = g_ellF[(node0 << 8) + i];
    for (int i = threadIdx.x; i < n1; i += 256) srow[1][i] = g_ellF[((node0 + 1) << 8) + i];
    __syncthreads();

    int n  = local ? n1 : n0;
    int jb = (n * q) >> 2;
    int je = (n * (q + 1)) >> 2;
    const __half* tabl = g_fxt16 + lane;

    part[local][q][lane] = spmm_smem(srow[local], tabl, jb, je);
    __syncthreads();

    if (q == 0) {
        float mu = (part[local][0][lane] + part[local][1][lane])
                 + (part[local][2][lane] + part[local][3][lane]);
        int node = node0 + local;
        int o = (node << 5) + lane;
        float eps = g_xt[o] - mu;
        g_epst[o]   = eps;
        g_epst16[o] = __float2half_rn(eps);
        out[lane * NV + node] = mu;                     // batch-major, scattered
        if (lane == 0) g_cnt_dst[node << 5] = 0;        // restore invariant
    }
}

// Backward SpMM: dx = -eps + (1-fx^2) * sum w * eps[dst];
// dx written straight to out[1] batch-major.
__global__ void __launch_bounds__(256, 8) k_dx(float* __restrict__ out) {
    __shared__ float2 srow[2][CAP];
    __shared__ float  part[2][4][32];
    int warp  = threadIdx.x >> 5;
    int lane  = threadIdx.x & 31;
    int local = warp >> 2;
    int q     = warp & 3;
    int node0 = blockIdx.x << 1;

    int n0 = min(g_cnt_src[node0 << 5],       CAP);
    int n1 = min(g_cnt_src[(node0 + 1) << 5], CAP);
    for (int i = threadIdx.x; i < n0; i += 256) srow[0][i] = g_ellB[(node0 << 8) + i];
    for (int i = threadIdx.x; i < n1; i += 256) srow[1][i] = g_ellB[((node0 + 1) << 8) + i];
    __syncthreads();

    int n  = local ? n1 : n0;
    int jb = (n * q) >> 2;
    int je = (n * (q + 1)) >> 2;
    const __half* tabl = g_epst16 + lane;

    part[local][q][lane] = spmm_smem(srow[local], tabl, jb, je);
    __syncthreads();

    if (q == 0) {
        float acc = (part[local][0][lane] + part[local][1][lane])
                  + (part[local][2][lane] + part[local][3][lane]);
        int node = node0 + local;
        int o = (node << 5) + lane;
        float eps = g_epst[o];
        float fx  = g_fxt[o];
        out[BN + lane * NV + node] = fmaf(fmaf(-fx, fx, 1.0f), acc, -eps);
        if (lane == 0) g_cnt_src[node << 5] = 0;        // restore invariant
    }
}

extern "C" void kernel_launch(void* const* d_in, const int* in_sizes, int n_in,
                              void* d_out, int out_size) {
    const float* x    = (const float*)d_in[0];
    const float* w    = (const float*)d_in[1];
    const int*   esrc = (const int*)d_in[2];
    const int*   edst = (const int*)d_in[3];
    float*       out  = (float*)d_out;
    int E = in_sizes[1];

    k_prep <<<NV / 32, 1024>>>(x);
    k_build<<<((E + 3) / 4 + 255) / 256, 256>>>(w, esrc, edst, E);
    k_mu   <<<NV / 2, 256>>>(out);
    k_dx   <<<NV / 2, 256>>>(out);
}

// round 12
// speedup vs baseline: 1.0008x; 1.0008x over previous
#include <cuda_runtime.h>
#include <cuda_fp16.h>

#define NV 4096            // nodes per graph
#define NB 32              // batch size (== warp size, load-bearing)
#define BN (NV * NB)       // 131072
#define CAP 256            // ELL row capacity (mean degree 128, +11 sigma headroom)
#define CSTRIDE 32         // counter padding: 1 counter per 128B line

// ---- scratch (device globals; counters zero at entry: BSS on first call,
//      self-zeroed by k_mu/k_dx on every call) ----
__device__ float  g_xt   [BN];           // x,  node-major [node][batch] (fp32)
__device__ float  g_fxt  [BN];           // tanh(x), node-major (fp32, epilogue)
__device__ __half g_fxt16[BN];           // tanh(x), node-major (fp16, gathers)
__device__ float  g_epst [BN];           // eps, node-major (fp32, epilogue)
__device__ __half g_epst16[BN];          // eps, node-major (fp16, gathers)
__device__ int    g_cnt_dst[NV * CSTRIDE];   // padded: index node*32
__device__ int    g_cnt_src[NV * CSTRIDE];
__device__ float2 g_ellF[NV * CAP];      // rows keyed by dst: (src*16, w)  [half2 units]
__device__ float2 g_ellB[NV * CAP];      // rows keyed by src: (dst*16, w)

// Transpose x [B,N] -> node-major, apply tanh (fp32 + fp16 copies).
__global__ void k_prep(const float* __restrict__ x) {
    __shared__ float s[32][33];
    int tx = threadIdx.x & 31;
    int ty = threadIdx.x >> 5;
    int i0 = blockIdx.x * 32;

    s[ty][tx] = x[ty * NV + i0 + tx];          // batch-major read (coalesced)
    __syncthreads();

    float xv = s[tx][ty];
    float fx = tanhf(xv);
    int o = (i0 + ty) * NB + tx;               // node-major write (coalesced)
    g_xt[o]    = xv;
    g_fxt[o]   = fx;
    g_fxt16[o] = __float2half_rn(fx);
}

// Build both ELL structures; 4 edges/thread, padded counters (R6-proven).
// Column offsets stored pre-scaled by 16 (half2 element granularity).
__global__ void k_build(const float* __restrict__ w,
                        const int*   __restrict__ esrc,
                        const int*   __restrict__ edst, int E) {
    int t  = blockIdx.x * blockDim.x + threadIdx.x;
    int e0 = t << 2;
    if (e0 >= E) return;
    if (e0 + 4 <= E) {
        int4   s4 = *(const int4*)  (esrc + e0);
        int4   d4 = *(const int4*)  (edst + e0);
        float4 w4 = *(const float4*)(w    + e0);
        int p0 = atomicAdd(&g_cnt_dst[d4.x << 5], 1);
        int p1 = atomicAdd(&g_cnt_dst[d4.y << 5], 1);
        int p2 = atomicAdd(&g_cnt_dst[d4.z << 5], 1);
        int p3 = atomicAdd(&g_cnt_dst[d4.w << 5], 1);
        int q0 = atomicAdd(&g_cnt_src[s4.x << 5], 1);
        int q1 = atomicAdd(&g_cnt_src[s4.y << 5], 1);
        int q2 = atomicAdd(&g_cnt_src[s4.z << 5], 1);
        int q3 = atomicAdd(&g_cnt_src[s4.w << 5], 1);
        if (p0 < CAP) g_ellF[(d4.x << 8) + p0] = make_float2(__int_as_float(s4.x << 4), w4.x);
        if (p1 < CAP) g_ellF[(d4.y << 8) + p1] = make_float2(__int_as_float(s4.y << 4), w4.y);
        if (p2 < CAP) g_ellF[(d4.z << 8) + p2] = make_float2(__int_as_float(s4.z << 4), w4.z);
        if (p3 < CAP) g_ellF[(d4.w << 8) + p3] = make_float2(__int_as_float(s4.w << 4), w4.w);
        if (q0 < CAP) g_ellB[(s4.x << 8) + q0] = make_float2(__int_as_float(d4.x << 4), w4.x);
        if (q1 < CAP) g_ellB[(s4.y << 8) + q1] = make_float2(__int_as_float(d4.y << 4), w4.y);
        if (q2 < CAP) g_ellB[(s4.z << 8) + q2] = make_float2(__int_as_float(d4.z << 4), w4.z);
        if (q3 < CAP) g_ellB[(s4.w << 8) + q3] = make_float2(__int_as_float(d4.w << 4), w4.w);
    } else {
        for (int e = e0; e < E; e++) {
            int s = esrc[e], d = edst[e];
            float wt = w[e];
            int p = atomicAdd(&g_cnt_dst[d << 5], 1);
            if (p < CAP) g_ellF[(d << 8) + p] = make_float2(__int_as_float(s << 4), wt);
            int q = atomicAdd(&g_cnt_src[s << 5], 1);
            if (q < CAP) g_ellB[(s << 8) + q] = make_float2(__int_as_float(d << 4), wt);
        }
    }
}

// ============================================================================
// Half-warp pair SpMM over smem-staged row, pair range [pb,pe):
// lane = (h, idx): half-warp h takes edge 2p+h of each pair, lane covers
// batches (2*idx, 2*idx+1) via one half2 gather. Unroll-8 pairs = 16 edges
// = 16 independent cache lines in flight per warp (2x the scalar loop).
// t2 is pre-offset per lane: (half2*)table + idx. Warp q==3 takes odd tail.
// Returns (s_even, s_odd) for batches (2*idx, 2*idx+1), reduced across halves.
// ============================================================================
__device__ __forceinline__ float2 spmm_pair(const float2* row,
                                            const __half2* __restrict__ t2,
                                            int pb, int pe, int n, int q, int h) {
    float ax0=0.f, ay0=0.f, ax1=0.f, ay1=0.f;
    float ax2=0.f, ay2=0.f, ax3=0.f, ay3=0.f;
    int p = pb;
    for (; p + 8 <= pe; p += 8) {
        float2 e0 = row[((p + 0) << 1) + h];
        float2 e1 = row[((p + 1) << 1) + h];
        float2 e2 = row[((p + 2) << 1) + h];
        float2 e3 = row[((p + 3) << 1) + h];
        float2 e4 = row[((p + 4) << 1) + h];
        float2 e5 = row[((p + 5) << 1) + h];
        float2 e6 = row[((p + 6) << 1) + h];
        float2 e7 = row[((p + 7) << 1) + h];
        __half2 v0 = t2[__float_as_int(e0.x)];
        __half2 v1 = t2[__float_as_int(e1.x)];
        __half2 v2 = t2[__float_as_int(e2.x)];
        __half2 v3 = t2[__float_as_int(e3.x)];
        __half2 v4 = t2[__float_as_int(e4.x)];
        __half2 v5 = t2[__float_as_int(e5.x)];
        __half2 v6 = t2[__float_as_int(e6.x)];
        __half2 v7 = t2[__float_as_int(e7.x)];
        float2 f0 = __half22float2(v0); float2 f1 = __half22float2(v1);
        float2 f2 = __half22float2(v2); float2 f3 = __half22float2(v3);
        float2 f4 = __half22float2(v4); float2 f5 = __half22float2(v5);
        float2 f6 = __half22float2(v6); float2 f7 = __half22float2(v7);
        ax0 = fmaf(e0.y, f0.x, ax0); ay0 = fmaf(e0.y, f0.y, ay0);
        ax1 = fmaf(e1.y, f1.x, ax1); ay1 = fmaf(e1.y, f1.y, ay1);
        ax2 = fmaf(e2.y, f2.x, ax2); ay2 = fmaf(e2.y, f2.y, ay2);
        ax3 = fmaf(e3.y, f3.x, ax3); ay3 = fmaf(e3.y, f3.y, ay3);
        ax0 = fmaf(e4.y, f4.x, ax0); ay0 = fmaf(e4.y, f4.y, ay0);
        ax1 = fmaf(e5.y, f5.x, ax1); ay1 = fmaf(e5.y, f5.y, ay1);
        ax2 = fmaf(e6.y, f6.x, ax2); ay2 = fmaf(e6.y, f6.y, ay2);
        ax3 = fmaf(e7.y, f7.x, ax3); ay3 = fmaf(e7.y, f7.y, ay3);
    }
    for (; p < pe; p++) {
        float2 e0 = row[(p << 1) + h];
        float2 f0 = __half22float2(t2[__float_as_int(e0.x)]);
        ax0 = fmaf(e0.y, f0.x, ax0); ay0 = fmaf(e0.y, f0.y, ay0);
    }
    if (q == 3 && (n & 1) && h == 0) {          // odd trailing edge, once
        float2 e0 = row[n - 1];
        float2 f0 = __half22float2(t2[__float_as_int(e0.x)]);
        ax0 = fmaf(e0.y, f0.x, ax0); ay0 = fmaf(e0.y, f0.y, ay0);
    }
    float sx = (ax0 + ax1) + (ax2 + ax3);
    float sy = (ay0 + ay1) + (ay2 + ay3);
    sx += __shfl_xor_sync(0xffffffffu, sx, 16);  // reduce across halves
    sy += __shfl_xor_sync(0xffffffffu, sy, 16);
    return make_float2(sx, sy);
}

// Forward SpMM: mu = sum w * fx[src]; eps = x - mu (fp32 + fp16);
// mu written straight to out[0] batch-major (scattered 4B stores).
__global__ void __launch_bounds__(256, 6) k_mu(float* __restrict__ out) {
    __shared__ float2 srow[2][CAP];
    __shared__ float  part[2][4][32];
    int warp  = threadIdx.x >> 5;
    int lane  = threadIdx.x & 31;
    int local = warp >> 2;
    int q     = warp & 3;
    int h     = lane >> 4;
    int idx   = lane & 15;
    int node0 = blockIdx.x << 1;

    int n0 = min(g_cnt_dst[node0 << 5],       CAP);
    int n1 = min(g_cnt_dst[(node0 + 1) << 5], CAP);
    for (int i = threadIdx.x; i < n0; i += 256) srow[0][i] = g_ellF[(node0 << 8) + i];
    for (int i = threadIdx.x; i < n1; i += 256) srow[1][i] = g_ellF[((node0 + 1) << 8) + i];
    __syncthreads();

    int n     = local ? n1 : n0;
    int npair = n >> 1;
    int pb    = (npair * q) >> 2;
    int pe    = (npair * (q + 1)) >> 2;
    const __half2* t2 = (const __half2*)g_fxt16 + idx;

    float2 s2 = spmm_pair(srow[local], t2, pb, pe, n, q, h);
    if (h == 0) {
        part[local][q][2 * idx]     = s2.x;
        part[local][q][2 * idx + 1] = s2.y;
    }
    __syncthreads();

    if (q == 0) {
        float mu = (part[local][0][lane] + part[local][1][lane])
                 + (part[local][2][lane] + part[local][3][lane]);
        int node = node0 + local;
        int o = (node << 5) + lane;
        float eps = g_xt[o] - mu;
        g_epst[o]   = eps;
        g_epst16[o] = __float2half_rn(eps);
        out[lane * NV + node] = mu;                     // batch-major, scattered
        if (lane == 0) g_cnt_dst[node << 5] = 0;        // restore invariant
    }
}

// Backward SpMM: dx = -eps + (1-fx^2) * sum w * eps[dst];
// dx written straight to out[1] batch-major.
__global__ void __launch_bounds__(256, 6) k_dx(float* __restrict__ out) {
    __shared__ float2 srow[2][CAP];
    __shared__ float  part[2][4][32];
    int warp  = threadIdx.x >> 5;
    int lane  = threadIdx.x & 31;
    int local = warp >> 2;
    int q     = warp & 3;
    int h     = lane >> 4;
    int idx   = lane & 15;
    int node0 = blockIdx.x << 1;

    int n0 = min(g_cnt_src[node0 << 5],       CAP);
    int n1 = min(g_cnt_src[(node0 + 1) << 5], CAP);
    for (int i = threadIdx.x; i < n0; i += 256) srow[0][i] = g_ellB[(node0 << 8) + i];
    for (int i = threadIdx.x; i < n1; i += 256) srow[1][i] = g_ellB[((node0 + 1) << 8) + i];
    __syncthreads();

    int n     = local ? n1 : n0;
    int npair = n >> 1;
    int pb    = (npair * q) >> 2;
    int pe    = (npair * (q + 1)) >> 2;
    const __half2* t2 = (const __half2*)g_epst16 + idx;

    float2 s2 = spmm_pair(srow[local], t2, pb, pe, n, q, h);
    if (h == 0) {
        part[local][q][2 * idx]     = s2.x;
        part[local][q][2 * idx + 1] = s2.y;
    }
    __syncthreads();

    if (q == 0) {
        float acc = (part[local][0][lane] + part[local][1][lane])
                  + (part[local][2][lane] + part[local][3][lane]);
        int node = node0 + local;
        int o = (node << 5) + lane;
        float eps = g_epst[o];
        float fx  = g_fxt[o];
        out[BN + lane * NV + node] = fmaf(fmaf(-fx, fx, 1.0f), acc, -eps);
        if (lane == 0) g_cnt_src[node << 5] = 0;        // restore invariant
    }
}

extern "C" void kernel_launch(void* const* d_in, const int* in_sizes, int n_in,
                              void* d_out, int out_size) {
    const float* x    = (const float*)d_in[0];
    const float* w    = (const float*)d_in[1];
    const int*   esrc = (const int*)d_in[2];
    const int*   edst = (const int*)d_in[3];
    float*       out  = (float*)d_out;
    int E = in_sizes[1];

    k_prep <<<NV / 32, 1024>>>(x);
    k_build<<<((E + 3) / 4 + 255) / 256, 256>>>(w, esrc, edst, E);
    k_mu   <<<NV / 2, 256>>>(out);
    k_dx   <<<NV / 2, 256>>>(out);
}